// round 11
// baseline (speedup 1.0000x reference)
#include <cuda_runtime.h>
#include <cuda_bf16.h>
#include <cstdint>
#include <cmath>

// ----------------------------------------------------------------------------
// Problem dims
// ----------------------------------------------------------------------------
#define NROWS 8192
#define DIM   1024
#define KDIM  2048   // 2*DIM

// GEMM tiling: CTA 128x128, 4 consumer warps (2x2, warp 64x64) + 1 producer
// warp. 3 stages, mbarrier full/empty pipeline, 2 CTA/SM.
#define M_TILE 128
#define N_TILE 128
#define K_TILE 64
#define NKT    (KDIM / K_TILE)    // 32
#define STAGES 3
#define A_BYTES (M_TILE * K_TILE * 2)     // 16384
#define B_BYTES (N_TILE * K_TILE * 2)     // 16384
#define ST_BYTES (A_BYTES + B_BYTES)      // 32768
#define MBAR_OFF (STAGES * ST_BYTES)      // 98304
#define SMEM_TOTAL (MBAR_OFF + 64)        // 98368
#define GEMM_THREADS 160

// ----------------------------------------------------------------------------
// Scratch (device globals: allocation-free rule)
// ----------------------------------------------------------------------------
__device__ __align__(1024) __nv_bfloat16 g_act[(size_t)NROWS * KDIM]; // 32 MB
__device__ __align__(1024) __nv_bfloat16 g_w2 [(size_t)DIM   * KDIM]; // 4 MB
__device__ __align__(16)   float g_cb0[DIM];
__device__ __align__(16)   float g_cb1[DIM];

// ----------------------------------------------------------------------------
// Helpers
// ----------------------------------------------------------------------------
__device__ __forceinline__ uint32_t smem_u32(const void* p) {
    uint32_t a;
    asm("{ .reg .u64 t; cvta.to.shared.u64 t, %1; cvt.u32.u64 %0, t; }" : "=r"(a) : "l"(p));
    return a;
}

__device__ __forceinline__ void cp_async16(uint32_t dst, const void* src) {
    asm volatile("cp.async.cg.shared.global [%0], [%1], 16;" :: "r"(dst), "l"(src) : "memory");
}

__device__ __forceinline__ void cp_async_mbar_arrive(uint32_t mbar) {
    asm volatile("cp.async.mbarrier.arrive.noinc.shared.b64 [%0];" :: "r"(mbar) : "memory");
}

#define MBAR_INIT(addr, cnt) \
    asm volatile("mbarrier.init.shared.b64 [%0], %1;" :: "r"((uint32_t)(addr)), "r"((uint32_t)(cnt)) : "memory")

#define MBAR_ARRIVE(addr) \
    asm volatile("mbarrier.arrive.shared.b64 _, [%0];" :: "r"((uint32_t)(addr)) : "memory")

__device__ __forceinline__ void mbar_wait(uint32_t mbar, uint32_t parity) {
    asm volatile(
        "{\n\t"
        ".reg .pred P;\n\t"
        "LAB_W_%=:\n\t"
        "mbarrier.try_wait.parity.acquire.cta.shared::cta.b64 P, [%0], %1, 0x989680;\n\t"
        "@P bra LAB_D_%=;\n\t"
        "bra LAB_W_%=;\n\t"
        "LAB_D_%=:\n\t"
        "}"
        :: "r"(mbar), "r"(parity) : "memory");
}

__device__ __forceinline__ void ldsm_x4(uint32_t* r, uint32_t addr) {
    asm volatile("ldmatrix.sync.aligned.m8n8.x4.shared.b16 {%0,%1,%2,%3}, [%4];"
                 : "=r"(r[0]), "=r"(r[1]), "=r"(r[2]), "=r"(r[3]) : "r"(addr));
}

__device__ __forceinline__ void mma_bf16(float* c, const uint32_t* a, const uint32_t* b) {
    asm volatile(
        "mma.sync.aligned.m16n8k16.row.col.f32.bf16.bf16.f32 "
        "{%0,%1,%2,%3}, {%4,%5,%6,%7}, {%8,%9}, {%0,%1,%2,%3};"
        : "+f"(c[0]), "+f"(c[1]), "+f"(c[2]), "+f"(c[3])
        : "r"(a[0]), "r"(a[1]), "r"(a[2]), "r"(a[3]), "r"(b[0]), "r"(b[1]));
}

__device__ __forceinline__ float gelu_fast(float a) {
    const float u = 0.7978845608028654f * a * (1.0f + 0.044715f * a * a);
    float t;
    asm("tanh.approx.f32 %0, %1;" : "=f"(t) : "f"(u));
    return 0.5f * a * (1.0f + t);
}

// ----------------------------------------------------------------------------
// Kernel 0: const contribution of tfeat_n/tfeat_a + bias
// ----------------------------------------------------------------------------
__global__ void __launch_bounds__(256) cbase_kernel(
    const float* __restrict__ tn, const float* __restrict__ ta,
    const float* __restrict__ convw, const float* __restrict__ convb)
{
    const int j = blockIdx.x * 256 + threadIdx.x;
    float c0 = convb[0], c1 = convb[1];
#pragma unroll
    for (int w = 0; w < 5; w++) {
        const int idx = j + w - 2;
        if (idx >= 0 && idx < DIM) {
            const float xn = tn[idx], xa = ta[idx];
            c0 += convw[0*15 + 0*5 + w] * xn + convw[0*15 + 1*5 + w] * xa;
            c1 += convw[1*15 + 0*5 + w] * xn + convw[1*15 + 1*5 + w] * xa;
        }
    }
    g_cb0[j] = c0;
    g_cb1[j] = c1;
}

// ----------------------------------------------------------------------------
// Kernel 1 (fused): blocks [0, NROWS): per-sample conv + cbase + GELU -> bf16
//                   blocks [NROWS, NROWS+2048): w2 fp32 -> bf16 convert
// ----------------------------------------------------------------------------
__global__ void __launch_bounds__(256) act_kernel(
    const float* __restrict__ ifeats, const float* __restrict__ convw,
    const float* __restrict__ w2)
{
    const int t = threadIdx.x;

    if (blockIdx.x >= NROWS) {
        const int idx = (blockIdx.x - NROWS) * 256 + t;
        const float4 v = ((const float4*)w2)[idx];
        __align__(8) __nv_bfloat16 o[4] = {
            __float2bfloat16_rn(v.x), __float2bfloat16_rn(v.y),
            __float2bfloat16_rn(v.z), __float2bfloat16_rn(v.w)
        };
        ((uint2*)g_w2)[idx] = *(uint2*)o;
        return;
    }

    __shared__ __align__(16) float s_in[DIM + 8];
    const int i = blockIdx.x;

    if (t < 4) { s_in[t] = 0.f; s_in[DIM + 4 + t] = 0.f; }
    ((float4*)(s_in + 4))[t] = ((const float4*)(ifeats + (size_t)i * DIM))[t];

    float wi0[5], wi1[5];
#pragma unroll
    for (int w = 0; w < 5; w++) {
        wi0[w] = __ldg(convw + 0*15 + 2*5 + w);
        wi1[w] = __ldg(convw + 1*15 + 2*5 + w);
    }
    const int j0 = t * 4;
    const float4 cb0 = *(const float4*)(g_cb0 + j0);
    const float4 cb1 = *(const float4*)(g_cb1 + j0);
    __syncthreads();

    float x[8];
#pragma unroll
    for (int q = 0; q < 8; q++) x[q] = s_in[j0 + 2 + q];

    __nv_bfloat16* outr = g_act + (size_t)i * KDIM;
    __align__(8) __nv_bfloat16 o0[4], o1[4];
    const float c0a[4] = { cb0.x, cb0.y, cb0.z, cb0.w };
    const float c1a[4] = { cb1.x, cb1.y, cb1.z, cb1.w };
#pragma unroll
    for (int jj = 0; jj < 4; jj++) {
        float a0 = c0a[jj], a1 = c1a[jj];
#pragma unroll
        for (int w = 0; w < 5; w++) {
            const float xi = x[jj + w];
            a0 += wi0[w] * xi;
            a1 += wi1[w] * xi;
        }
        o0[jj] = __float2bfloat16_rn(gelu_fast(a0));
        o1[jj] = __float2bfloat16_rn(gelu_fast(a1));
    }
    *(uint2*)(outr + j0)       = *(uint2*)o0;
    *(uint2*)(outr + DIM + j0) = *(uint2*)o1;
}

// ----------------------------------------------------------------------------
// Kernel 3: warp-specialized mma.sync bf16 GEMM.
// 160 threads: warps 0-3 consumers (2x2 of 64x64), warp 4 producer (all
// cp.async). mbarrier full(count 32, cp.async.mbarrier.arrive.noinc) /
// empty(count 4) per stage, 3 stages, 2 CTA/SM.
//   out[m,n] = ifeats[m,n] + b2[n] + sum_k g_act[m,k] * g_w2[n,k]
// ----------------------------------------------------------------------------
__global__ void __launch_bounds__(GEMM_THREADS, 2) gemm_kernel(
    const float* __restrict__ ifeats,
    const float* __restrict__ b2,
    float* __restrict__ out)
{
    extern __shared__ __align__(1024) char smem[];
    const uint32_t sb = smem_u32(smem);
    const int tid  = threadIdx.x;
    const int lane = tid & 31;
    const int wid  = tid >> 5;
    const int m0   = blockIdx.y * M_TILE;
    const int n0   = blockIdx.x * N_TILE;

    const uint32_t mb_full  = sb + MBAR_OFF;       // full[s]  at +s*8
    const uint32_t mb_empty = sb + MBAR_OFF + 32;  // empty[s] at +32+s*8

    if (tid == 0) {
#pragma unroll
        for (int s = 0; s < STAGES; s++) {
            MBAR_INIT(mb_full  + s * 8, 32);  // producer lanes
            MBAR_INIT(mb_empty + s * 8, 4);   // consumer warps
        }
    }
    __syncthreads();

    if (wid == 4) {
        // ------------------------- producer warp -------------------------
        const int rb = lane >> 3;          // 0..3
        const int kc = lane & 7;
        const __nv_bfloat16* gA = g_act + (size_t)(m0 + rb) * KDIM + kc * 8;
        const __nv_bfloat16* gB = g_w2  + (size_t)(n0 + rb) * KDIM + kc * 8;
        // row = rb + 4*i: (row & 7) alternates rb (i even) / rb+4 (i odd)
        const uint32_t sw_lo = (uint32_t)((kc * 16) ^ (rb << 4));
        const uint32_t sw_hi = (uint32_t)((kc * 16) ^ ((rb + 4) << 4));

        int ps = 0, pph = 1;
#pragma unroll 1
        for (int kt = 0; kt < NKT; kt++) {
            mbar_wait(mb_empty + ps * 8, (uint32_t)pph);
            const uint32_t base = sb + (uint32_t)ps * ST_BYTES;
            const __nv_bfloat16* a = gA + (size_t)kt * K_TILE;
            const __nv_bfloat16* b = gB + (size_t)kt * K_TILE;
#pragma unroll
            for (int i = 0; i < 32; i++) {
                const uint32_t row128 = (uint32_t)((rb + 4 * i) * 128);
                const uint32_t sw = (i & 1) ? sw_hi : sw_lo;
                cp_async16(base + row128 + sw, a + (size_t)(4 * i) * KDIM);
            }
#pragma unroll
            for (int i = 0; i < 32; i++) {
                const uint32_t row128 = (uint32_t)((rb + 4 * i) * 128);
                const uint32_t sw = (i & 1) ? sw_hi : sw_lo;
                cp_async16(base + A_BYTES + row128 + sw, b + (size_t)(4 * i) * KDIM);
            }
            cp_async_mbar_arrive(mb_full + ps * 8);
            if (++ps == STAGES) { ps = 0; pph ^= 1; }
        }
        return;
    }

    // --------------------------- consumer warps ---------------------------
    const int wm = wid & 1;     // 2 warp rows -> 64 m each
    const int wn = wid >> 1;    // 2 warp cols -> 64 n each

    float acc[4][8][4];
#pragma unroll
    for (int a = 0; a < 4; a++)
#pragma unroll
        for (int b = 0; b < 8; b++)
#pragma unroll
            for (int q = 0; q < 4; q++) acc[a][b][q] = 0.f;

    const uint32_t xsw   = (uint32_t)((lane & 7) << 4);
    const int rowA = wm * 64 + (lane & 7) + ((lane & 8) ? 8 : 0);
    const uint32_t colA0 = (uint32_t)(((lane >> 4) & 1) << 4);
    const int rowB = wn * 64 + (lane & 7) + ((lane & 16) ? 8 : 0);
    const uint32_t colB0 = (uint32_t)(((lane >> 3) & 1) << 4);

    int cs = 0, cph = 0;
#pragma unroll 1
    for (int kt = 0; kt < NKT; kt++) {
        mbar_wait(mb_full + cs * 8, (uint32_t)cph);
        const uint32_t aBase = sb + (uint32_t)cs * ST_BYTES;
        const uint32_t bBase = aBase + A_BYTES;

#pragma unroll
        for (int ks = 0; ks < 4; ks++) {
            const uint32_t kcol = (uint32_t)(ks * 32);
            uint32_t af[4][4];
#pragma unroll
            for (int mt = 0; mt < 4; mt++)
                ldsm_x4(af[mt], aBase + (uint32_t)((rowA + mt * 16) * 128)
                                      + ((kcol + colA0) ^ xsw));
            uint32_t bf[4][4];
#pragma unroll
            for (int p = 0; p < 4; p++)
                ldsm_x4(bf[p], bBase + (uint32_t)((rowB + p * 16) * 128)
                                     + ((kcol + colB0) ^ xsw));
#pragma unroll
            for (int mt = 0; mt < 4; mt++)
#pragma unroll
                for (int nt = 0; nt < 8; nt++)
                    mma_bf16(acc[mt][nt], af[mt], &bf[nt >> 1][(nt & 1) * 2]);
        }

        if (lane == 0) MBAR_ARRIVE(mb_empty + cs * 8);
        if (++cs == STAGES) { cs = 0; cph ^= 1; }
    }

    // epilogue: out = ifeats + b2 + acc
#pragma unroll
    for (int mt = 0; mt < 4; mt++) {
#pragma unroll
        for (int nt = 0; nt < 8; nt++) {
            const int r0 = m0 + wm * 64 + mt * 16 + (lane >> 2);
            const int c0 = n0 + wn * 64 + nt * 8 + ((lane & 3) << 1);
            const float2 bv = *(const float2*)(b2 + c0);
            {
                const float2 iv = *(const float2*)(ifeats + (size_t)r0 * DIM + c0);
                float2 ov;
                ov.x = iv.x + bv.x + acc[mt][nt][0];
                ov.y = iv.y + bv.y + acc[mt][nt][1];
                *(float2*)(out + (size_t)r0 * DIM + c0) = ov;
            }
            {
                const int r1 = r0 + 8;
                const float2 iv = *(const float2*)(ifeats + (size_t)r1 * DIM + c0);
                float2 ov;
                ov.x = iv.x + bv.x + acc[mt][nt][2];
                ov.y = iv.y + bv.y + acc[mt][nt][3];
                *(float2*)(out + (size_t)r1 * DIM + c0) = ov;
            }
        }
    }
}

// ----------------------------------------------------------------------------
// Host launcher
// ----------------------------------------------------------------------------
extern "C" void kernel_launch(void* const* d_in, const int* in_sizes, int n_in,
                              void* d_out, int out_size)
{
    const float* ifeats = (const float*)d_in[0];
    const float* tn     = (const float*)d_in[1];
    const float* ta     = (const float*)d_in[2];
    const float* convw  = (const float*)d_in[3];
    const float* convb  = (const float*)d_in[4];
    const float* w2     = (const float*)d_in[5];
    const float* b2     = (const float*)d_in[6];
    float* out = (float*)d_out;

    cbase_kernel<<<DIM / 256, 256>>>(tn, ta, convw, convb);
    act_kernel<<<NROWS + (DIM * KDIM / 4) / 256, 256>>>(ifeats, convw, w2);

    static bool attr_set = false;
    if (!attr_set) {
        cudaFuncSetAttribute(gemm_kernel, cudaFuncAttributeMaxDynamicSharedMemorySize, SMEM_TOTAL);
        attr_set = true;
    }
    gemm_kernel<<<dim3(DIM / N_TILE, NROWS / M_TILE), GEMM_THREADS, SMEM_TOTAL>>>(ifeats, b2, out);

    (void)in_sizes; (void)n_in; (void)out_size;
}

// round 12
// speedup vs baseline: 1.1788x; 1.1788x over previous
#include <cuda_runtime.h>
#include <cuda_bf16.h>
#include <cstdint>
#include <cmath>

// ----------------------------------------------------------------------------
// Problem dims
// ----------------------------------------------------------------------------
#define NROWS 8192
#define DIM   1024
#define KDIM  2048   // 2*DIM

// GEMM tiling: CTA 128x128, 4 warps (2m x 2n), warp 64x64, K=64/stage, 3 stages
#define M_TILE 128
#define N_TILE 128
#define K_TILE 64
#define NKT    (KDIM / K_TILE)    // 32
#define STAGES 3
#define A_BYTES (M_TILE * K_TILE * 2)     // 16384
#define B_BYTES (N_TILE * K_TILE * 2)     // 16384
#define ST_BYTES (A_BYTES + B_BYTES)      // 32768
#define SMEM_TOTAL (STAGES * ST_BYTES)    // 98304

// act kernel: 2 rows per block
#define ACT_CONV_BLOCKS (NROWS / 2)                 // 4096
#define W2CVT_BLOCKS    ((DIM * KDIM / 8) / 256)    // 1024 (8 elems/thread)

// ----------------------------------------------------------------------------
// Scratch (device globals: allocation-free rule)
// ----------------------------------------------------------------------------
__device__ __align__(1024) __nv_bfloat16 g_act[(size_t)NROWS * KDIM]; // 32 MB
__device__ __align__(1024) __nv_bfloat16 g_w2 [(size_t)DIM   * KDIM]; // 4 MB
__device__ __align__(16)   float g_cb0[DIM];
__device__ __align__(16)   float g_cb1[DIM];

// ----------------------------------------------------------------------------
// Helpers
// ----------------------------------------------------------------------------
__device__ __forceinline__ uint32_t smem_u32(const void* p) {
    uint32_t a;
    asm("{ .reg .u64 t; cvta.to.shared.u64 t, %1; cvt.u32.u64 %0, t; }" : "=r"(a) : "l"(p));
    return a;
}

__device__ __forceinline__ void cp_async16(uint32_t dst, const void* src) {
    asm volatile("cp.async.cg.shared.global [%0], [%1], 16;" :: "r"(dst), "l"(src) : "memory");
}
#define CP_COMMIT() asm volatile("cp.async.commit_group;" ::: "memory")
#define CP_WAIT(n)  asm volatile("cp.async.wait_group %0;" :: "n"(n) : "memory")

__device__ __forceinline__ void ldsm_x4(uint32_t* r, uint32_t addr) {
    asm volatile("ldmatrix.sync.aligned.m8n8.x4.shared.b16 {%0,%1,%2,%3}, [%4];"
                 : "=r"(r[0]), "=r"(r[1]), "=r"(r[2]), "=r"(r[3]) : "r"(addr));
}

__device__ __forceinline__ void mma_bf16(float* c, const uint32_t* a, const uint32_t* b) {
    asm volatile(
        "mma.sync.aligned.m16n8k16.row.col.f32.bf16.bf16.f32 "
        "{%0,%1,%2,%3}, {%4,%5,%6,%7}, {%8,%9}, {%0,%1,%2,%3};"
        : "+f"(c[0]), "+f"(c[1]), "+f"(c[2]), "+f"(c[3])
        : "r"(a[0]), "r"(a[1]), "r"(a[2]), "r"(a[3]), "r"(b[0]), "r"(b[1]));
}

__device__ __forceinline__ float gelu_fast(float a) {
    const float u = 0.7978845608028654f * a * (1.0f + 0.044715f * a * a);
    float t;
    asm("tanh.approx.f32 %0, %1;" : "=f"(t) : "f"(u));
    return 0.5f * a * (1.0f + t);
}

// ----------------------------------------------------------------------------
// Kernel 0: const contribution of tfeat_n/tfeat_a + bias
// ----------------------------------------------------------------------------
__global__ void __launch_bounds__(256) cbase_kernel(
    const float* __restrict__ tn, const float* __restrict__ ta,
    const float* __restrict__ convw, const float* __restrict__ convb)
{
    const int j = blockIdx.x * 256 + threadIdx.x;
    float c0 = convb[0], c1 = convb[1];
#pragma unroll
    for (int w = 0; w < 5; w++) {
        const int idx = j + w - 2;
        if (idx >= 0 && idx < DIM) {
            const float xn = tn[idx], xa = ta[idx];
            c0 += convw[0*15 + 0*5 + w] * xn + convw[0*15 + 1*5 + w] * xa;
            c1 += convw[1*15 + 0*5 + w] * xn + convw[1*15 + 1*5 + w] * xa;
        }
    }
    g_cb0[j] = c0;
    g_cb1[j] = c1;
}

// ----------------------------------------------------------------------------
// Kernel 1 (fused): blocks [0, ACT_CONV_BLOCKS): conv+cbase+GELU for 2 rows
//                   blocks [ACT_CONV_BLOCKS, +W2CVT_BLOCKS): w2 fp32->bf16
// ----------------------------------------------------------------------------
__global__ void __launch_bounds__(256) act_kernel(
    const float* __restrict__ ifeats, const float* __restrict__ convw,
    const float* __restrict__ w2)
{
    const int t = threadIdx.x;

    if (blockIdx.x >= ACT_CONV_BLOCKS) {
        // w2 convert: 8 elems per thread
        const int idx = ((blockIdx.x - ACT_CONV_BLOCKS) * 256 + t) * 2;
#pragma unroll
        for (int u = 0; u < 2; u++) {
            const float4 v = ((const float4*)w2)[idx + u];
            __align__(8) __nv_bfloat16 o[4] = {
                __float2bfloat16_rn(v.x), __float2bfloat16_rn(v.y),
                __float2bfloat16_rn(v.z), __float2bfloat16_rn(v.w)
            };
            ((uint2*)g_w2)[idx + u] = *(uint2*)o;
        }
        return;
    }

    __shared__ __align__(16) float s_in[2][DIM + 8];
    const int i0 = blockIdx.x * 2;

    if (t < 4) {
        s_in[0][t] = 0.f; s_in[0][DIM + 4 + t] = 0.f;
        s_in[1][t] = 0.f; s_in[1][DIM + 4 + t] = 0.f;
    }
    ((float4*)(s_in[0] + 4))[t] = ((const float4*)(ifeats + (size_t)i0 * DIM))[t];
    ((float4*)(s_in[1] + 4))[t] = ((const float4*)(ifeats + (size_t)(i0 + 1) * DIM))[t];

    float wi0[5], wi1[5];
#pragma unroll
    for (int w = 0; w < 5; w++) {
        wi0[w] = __ldg(convw + 0*15 + 2*5 + w);
        wi1[w] = __ldg(convw + 1*15 + 2*5 + w);
    }
    const int j0 = t * 4;
    const float4 cb0 = *(const float4*)(g_cb0 + j0);
    const float4 cb1 = *(const float4*)(g_cb1 + j0);
    const float c0a[4] = { cb0.x, cb0.y, cb0.z, cb0.w };
    const float c1a[4] = { cb1.x, cb1.y, cb1.z, cb1.w };
    __syncthreads();

#pragma unroll
    for (int r = 0; r < 2; r++) {
        float x[8];
#pragma unroll
        for (int q = 0; q < 8; q++) x[q] = s_in[r][j0 + 2 + q];

        __nv_bfloat16* outr = g_act + (size_t)(i0 + r) * KDIM;
        __align__(8) __nv_bfloat16 o0[4], o1[4];
#pragma unroll
        for (int jj = 0; jj < 4; jj++) {
            float a0 = c0a[jj], a1 = c1a[jj];
#pragma unroll
            for (int w = 0; w < 5; w++) {
                const float xi = x[jj + w];
                a0 += wi0[w] * xi;
                a1 += wi1[w] * xi;
            }
            o0[jj] = __float2bfloat16_rn(gelu_fast(a0));
            o1[jj] = __float2bfloat16_rn(gelu_fast(a1));
        }
        *(uint2*)(outr + j0)       = *(uint2*)o0;
        *(uint2*)(outr + DIM + j0) = *(uint2*)o1;
    }
}

// ----------------------------------------------------------------------------
// Kernel 3: mma.sync bf16 GEMM (R8 structure: 3-stage, cross-kt frag pipeline,
// split A/B copy issue). CTA 128x128, 128 threads, 4 warps (2x2), warp 64x64,
// 2 CTA/SM.
//   out[m,n] = ifeats[m,n] + b2[n] + sum_k g_act[m,k] * g_w2[n,k]
// ----------------------------------------------------------------------------
__device__ __forceinline__ void issue_half(uint32_t dst, const __nv_bfloat16* g)
{
#pragma unroll
    for (int i = 0; i < 8; i++)
        cp_async16(dst + (uint32_t)(i * 16 * 128), g + (size_t)(i * 16) * KDIM);
}

__global__ void __launch_bounds__(128, 2) gemm_kernel(
    const float* __restrict__ ifeats,
    const float* __restrict__ b2,
    float* __restrict__ out)
{
    extern __shared__ __align__(1024) char smem[];
    const uint32_t sb = smem_u32(smem);
    const int tid  = threadIdx.x;
    const int lane = tid & 31;
    const int wid  = tid >> 5;
    const int wm   = wid & 1;     // 2 warp rows -> 64 m each
    const int wn   = wid >> 1;    // 2 warp cols -> 64 n each
    const int m0   = blockIdx.y * M_TILE;
    const int n0   = blockIdx.x * N_TILE;

    // per-thread cp.async bases
    const int ldrow = tid >> 3;          // 0..15
    const int ldkc  = tid & 7;
    const uint32_t ldsw = (uint32_t)((ldkc * 16) ^ ((ldrow & 7) << 4));
    const uint32_t dA0 = sb + (uint32_t)(ldrow * 128) + ldsw;
    const uint32_t dB0 = dA0 + A_BYTES;
    const __nv_bfloat16* gA0 = g_act + (size_t)(m0 + ldrow) * KDIM + ldkc * 8;
    const __nv_bfloat16* gB0 = g_w2  + (size_t)(n0 + ldrow) * KDIM + ldkc * 8;

    float acc[4][8][4];
#pragma unroll
    for (int a = 0; a < 4; a++)
#pragma unroll
        for (int b = 0; b < 8; b++)
#pragma unroll
            for (int q = 0; q < 4; q++) acc[a][b][q] = 0.f;

    const uint32_t xsw   = (uint32_t)((lane & 7) << 4);
    const int rowA = wm * 64 + (lane & 7) + ((lane & 8) ? 8 : 0);
    const uint32_t colA0 = (uint32_t)(((lane >> 4) & 1) << 4);
    const int rowB = wn * 64 + (lane & 7) + ((lane & 16) ? 8 : 0);
    const uint32_t colB0 = (uint32_t)(((lane >> 3) & 1) << 4);

    uint32_t af[2][4][4];
    uint32_t bf[2][4][4];

    // prologue: stages 0,1
    issue_half(dA0, gA0); issue_half(dB0, gB0); CP_COMMIT();
    issue_half(dA0 + ST_BYTES, gA0 + K_TILE);
    issue_half(dB0 + ST_BYTES, gB0 + K_TILE); CP_COMMIT();
    CP_WAIT(1);
    __syncthreads();

    // preload kt=0 ks=0 fragments into buf 0
#pragma unroll
    for (int mt = 0; mt < 4; mt++)
        ldsm_x4(af[0][mt], sb + (uint32_t)((rowA + mt * 16) * 128) + (colA0 ^ xsw));
#pragma unroll
    for (int p = 0; p < 4; p++)
        ldsm_x4(bf[0][p], sb + A_BYTES + (uint32_t)((rowB + p * 16) * 128) + (colB0 ^ xsw));

#pragma unroll 1
    for (int kt = 0; kt < NKT; kt++) {
        const uint32_t aBase = sb + (uint32_t)(kt % STAGES) * ST_BYTES;
        const uint32_t bBase = aBase + A_BYTES;
        const uint32_t offN  = (uint32_t)((kt + 2) % STAGES) * ST_BYTES;

#pragma unroll
        for (int ks = 0; ks < 4; ks++) {
            const int cur = ks & 1, nxt = cur ^ 1;

            // 1) fragment prefetch for next k-step (or next stage at ks3)
            if (ks < 3) {
                const uint32_t kcol = (uint32_t)((ks + 1) * 32);
#pragma unroll
                for (int mt = 0; mt < 4; mt++)
                    ldsm_x4(af[nxt][mt], aBase + (uint32_t)((rowA + mt * 16) * 128)
                                               + ((kcol + colA0) ^ xsw));
#pragma unroll
                for (int p = 0; p < 4; p++)
                    ldsm_x4(bf[nxt][p], bBase + (uint32_t)((rowB + p * 16) * 128)
                                              + ((kcol + colB0) ^ xsw));
            } else {
                CP_WAIT(1);
                __syncthreads();
                if (kt + 1 < NKT) {
                    const uint32_t aN = sb + (uint32_t)((kt + 1) % STAGES) * ST_BYTES;
                    const uint32_t bN = aN + A_BYTES;
#pragma unroll
                    for (int mt = 0; mt < 4; mt++)
                        ldsm_x4(af[nxt][mt], aN + (uint32_t)((rowA + mt * 16) * 128)
                                                + (colA0 ^ xsw));
#pragma unroll
                    for (int p = 0; p < 4; p++)
                        ldsm_x4(bf[nxt][p], bN + (uint32_t)((rowB + p * 16) * 128)
                                               + (colB0 ^ xsw));
                }
            }

            // 2) MMAs for current k-step
#pragma unroll
            for (int mt = 0; mt < 4; mt++)
#pragma unroll
                for (int nt = 0; nt < 8; nt++)
                    mma_bf16(acc[mt][nt], af[cur][mt], &bf[cur][nt >> 1][(nt & 1) * 2]);

            // 3) copy issue behind the MMA shadow: A at ks0, B at ks1
            if (ks == 0) {
                if (kt + 2 < NKT)
                    issue_half(dA0 + offN, gA0 + (size_t)(kt + 2) * K_TILE);
            } else if (ks == 1) {
                if (kt + 2 < NKT)
                    issue_half(dB0 + offN, gB0 + (size_t)(kt + 2) * K_TILE);
                CP_COMMIT();
            }
        }
    }

    // epilogue: out = ifeats + b2 + acc  (b2 hoisted out of mt loop)
    const int cbase = n0 + wn * 64 + ((lane & 3) << 1);
    float2 bv[8];
#pragma unroll
    for (int nt = 0; nt < 8; nt++)
        bv[nt] = *(const float2*)(b2 + cbase + nt * 8);

#pragma unroll
    for (int mt = 0; mt < 4; mt++) {
        const int r0 = m0 + wm * 64 + mt * 16 + (lane >> 2);
        const float* i0p = ifeats + (size_t)r0 * DIM;
        const float* i1p = i0p + (size_t)8 * DIM;
        float* o0p = out + (size_t)r0 * DIM;
        float* o1p = o0p + (size_t)8 * DIM;
#pragma unroll
        for (int nt = 0; nt < 8; nt++) {
            const int c0 = cbase + nt * 8;
            {
                const float2 iv = *(const float2*)(i0p + c0);
                float2 ov;
                ov.x = iv.x + bv[nt].x + acc[mt][nt][0];
                ov.y = iv.y + bv[nt].y + acc[mt][nt][1];
                *(float2*)(o0p + c0) = ov;
            }
            {
                const float2 iv = *(const float2*)(i1p + c0);
                float2 ov;
                ov.x = iv.x + bv[nt].x + acc[mt][nt][2];
                ov.y = iv.y + bv[nt].y + acc[mt][nt][3];
                *(float2*)(o1p + c0) = ov;
            }
        }
    }
}

// ----------------------------------------------------------------------------
// Host launcher
// ----------------------------------------------------------------------------
extern "C" void kernel_launch(void* const* d_in, const int* in_sizes, int n_in,
                              void* d_out, int out_size)
{
    const float* ifeats = (const float*)d_in[0];
    const float* tn     = (const float*)d_in[1];
    const float* ta     = (const float*)d_in[2];
    const float* convw  = (const float*)d_in[3];
    const float* convb  = (const float*)d_in[4];
    const float* w2     = (const float*)d_in[5];
    const float* b2     = (const float*)d_in[6];
    float* out = (float*)d_out;

    cbase_kernel<<<DIM / 256, 256>>>(tn, ta, convw, convb);
    act_kernel<<<ACT_CONV_BLOCKS + W2CVT_BLOCKS, 256>>>(ifeats, convw, w2);

    static bool attr_set = false;
    if (!attr_set) {
        cudaFuncSetAttribute(gemm_kernel, cudaFuncAttributeMaxDynamicSharedMemorySize, SMEM_TOTAL);
        attr_set = true;
    }
    gemm_kernel<<<dim3(DIM / N_TILE, NROWS / M_TILE), 128, SMEM_TOTAL>>>(ifeats, b2, out);

    (void)in_sizes; (void)n_in; (void)out_size;
}